// round 15
// baseline (speedup 1.0000x reference)
#include <cuda_runtime.h>
#include <cuda_fp16.h>
#include <math_constants.h>

#define HH 512
#define WW 512
#define BB 16
// window p=35, pad=17
// loss = mean(erosion_35x35(min_c x)) - 1   (erosion = separable min filter)

// Intermediate: vertically eroded field, [B][H][W/2], half2 packs (w, w+1)
__device__ __align__(16) __half2 g_t2[BB * HH * WW / 2];
// Per-block partial sums from kernel 2 (1024 blocks)
__device__ float g_partial[1024];

// ---------------------------------------------------------------------------
// Kernel 1: channel-min of x (fp32 -> fp16) fused with vertical min-filter,
// FULL-COLUMN (zero halo: irreducible 50.3MB input read) x 256-THREAD blocks
// (R12's loader occupancy: ~28 warps/SM). Strip = 16 W cols x 512 rows
// (+17 INF pad each side -> 560 tile rows, 17.9KB smem).
// Block = (8 half2 lanes, 32) = 256 thr; all threads load; chains on ty<15.
// grid = (W/16, B) = 512 blocks.
// ---------------------------------------------------------------------------
__global__ __launch_bounds__(256) void k1_vert(const float* __restrict__ x) {
    __shared__ __half2 sm[560 * 8];           // [tile row][8 half2 = 16 cols]

    const int tx  = threadIdx.x;              // half2 lane 0..7
    const int ty  = threadIdx.y;              // 0..31
    const int tid = ty * 8 + tx;
    const int wc0 = blockIdx.x * 16;
    const int b   = blockIdx.y;
    const float INF = CUDART_INF_F;

    // Load channel-min of the whole column strip: tile rows [0,560),
    // image row gh = r - 17; rows outside [0,512) -> +INF.
    const float* xb = x + (size_t)b * 3 * HH * WW;
    for (int j = tid; j < 560 * 4; j += 256) {
        int r  = j >> 2;
        int c4 = j & 3;                       // float4 slot (4 per row)
        int gh = r - 17;
        float4 m;
        if ((unsigned)gh < HH) {
            const float4* p = (const float4*)(xb + (size_t)gh * WW + wc0 + c4 * 4);
            float4 a0 = p[0];
            float4 a1 = p[(HH * WW) / 4];
            float4 a2 = p[(2 * HH * WW) / 4];
            m.x = fminf(a0.x, fminf(a1.x, a2.x));
            m.y = fminf(a0.y, fminf(a1.y, a2.y));
            m.z = fminf(a0.z, fminf(a1.z, a2.z));
            m.w = fminf(a0.w, fminf(a1.w, a2.w));
        } else {
            m = make_float4(INF, INF, INF, INF);
        }
        __half2 h0 = __floats2half2_rn(m.x, m.y);
        __half2 h1 = __floats2half2_rn(m.z, m.w);
        uint2 pk = make_uint2(*(unsigned*)&h0, *(unsigned*)&h1);
        *(uint2*)&sm[r * 8 + c4 * 2] = pk;    // STS.64
    }
    __syncthreads();

    // Chains: ty < 15, chunk c = ty, base = 35c, tile row of base = 35c+17.
    if (ty >= 15) return;
    const int base = 35 * ty;
    const int lb   = 35 * ty + 17;
    const __half2 HINF = __float2half2_rn(CUDART_INF_F);

    // Pass 1: suffix minima (segment reset at k==35, crossing into chunk c-1)
    __half2 S[35];
    __half2 run = HINF;
    #pragma unroll
    for (int k = 0; k < 52; k++) {
        if (k == 35) run = HINF;
        run = __hmin2(run, sm[(lb + 34 - k) * 8 + tx]);
        if (k >= 17) S[51 - k] = run;
    }

    // Pass 2: prefix minima, combine + store on the fly
    run = HINF;
    const size_t ob = (size_t)b * HH;
    const int wcol = blockIdx.x * 8 + tx;     // half2 column
    #pragma unroll
    for (int k = 0; k < 52; k++) {
        if (k == 35) run = HINF;
        run = __hmin2(run, sm[(lb + k) * 8 + tx]);
        if (k >= 17) {
            int i = base + k - 17;
            if (i < HH)
                g_t2[(ob + i) * (WW / 2) + wcol] = __hmin2(S[k - 17], run);
        }
    }
}

// ---------------------------------------------------------------------------
// Kernel 2: horizontal min-filter in PAIR DOMAIN, chunk length 36 (verified
// round-9 math), register-resident chains: 18 independent predicated LDG.64
// per thread, then pure register suffix/prefix/combine.
// Thread (tx = chunk slot 0..15, ty = row 0..7); grid = (H/8, B).
// ---------------------------------------------------------------------------
__global__ __launch_bounds__(128) void k2_horiz() {
    __shared__ float red[128];

    const int tx  = threadIdx.x;              // chunk slot 0..15 (t = tx-1)
    const int ty  = threadIdx.y;              // row-in-tile 0..7
    const int tid = ty * 16 + tx;
    const int h0  = blockIdx.x * 8;
    const int b   = blockIdx.y;
    const __half2 HINF2 = __float2half2_rn(CUDART_INF_F);
    const unsigned INFU = 0x7C007C00u;

    const int t = tx - 1;                     // -1..14
    const __half2* rowp = g_t2 + (size_t)(b * HH + h0 + ty) * (WW / 2);

    // Load chunk t (pairs [18t, 18t+18)) and chunk t+1 into registers.
    __half2 ct[18], dt[18];
    #pragma unroll
    for (int j = 0; j < 9; j++) {
        int p0 = 18 * t + 2 * j;
        uint2 v = make_uint2(INFU, INFU);
        if ((unsigned)p0 < 256u) v = *(const uint2*)(rowp + p0);
        ct[2 * j]     = *(__half2*)&v.x;
        ct[2 * j + 1] = *(__half2*)&v.y;
    }
    #pragma unroll
    for (int j = 0; j < 9; j++) {
        int p0 = 18 * (t + 1) + 2 * j;
        uint2 v = make_uint2(INFU, INFU);
        if ((unsigned)p0 < 256u) v = *(const uint2*)(rowp + p0);
        dt[2 * j]     = *(__half2*)&v.x;
        dt[2 * j + 1] = *(__half2*)&v.y;
    }

    // Backward: suffix pair-minima over chunk t
    __half2 SR[18];
    {
        __half2 run = HINF2;
        #pragma unroll
        for (int u = 17; u >= 0; u--) {
            run = __hmin2(run, ct[u]);
            SR[u] = run;
        }
    }

    // Forward over chunk t+1 + parity combine + accumulate
    __half2 hacc = __float2half2_rn(0.0f);
    __half2 Rp  = HINF2;                      // R[n-1]
    __half2 HPp = HINF2;                      // hmin(R[n-1]) broadcast
    const int obase = 36 * t + 18;
    #pragma unroll
    for (int n = 0; n < 18; n++) {
        __half2 v  = dt[n];
        __half2 Rc = __hmin2(Rp, v);          // R[n]
        __half2 srn = (n < 17) ? SR[n + 1] : HINF2;
        unsigned srnu = *(unsigned*)&srn;
        unsigned swp  = __byte_perm(srnu, srnu, 0x1032);
        __half2 hs = __hmin2(srn, *(__half2*)&swp);   // H_S[n+1] broadcast
        unsigned sru = *(unsigned*)&SR[n];
        unsigned Rcu = *(unsigned*)&Rc;
        unsigned Rpu = *(unsigned*)&Rp;
        unsigned HPu = *(unsigned*)&HPp;
        unsigned Au = __byte_perm(sru, Rcu, 0x5432);  // (SR[n].hi, Rc.lo)
        unsigned Bu = __byte_perm(HPu, Rpu, 0x7610);  // (HPp,      Rp.hi)
        __half2 o = __hmin2(__hmin2(*(__half2*)&Au, *(__half2*)&Bu), hs);
        if ((unsigned)(obase + 2 * n) < 512u)
            hacc = __hadd2(hacc, o);
        unsigned rs = __byte_perm(Rcu, Rcu, 0x1032);
        HPp = __hmin2(Rc, *(__half2*)&rs);    // hmin(R[n]) broadcast
        Rp = Rc;
    }
    float2 e2 = __half22float2(hacc);
    float acc = e2.x + e2.y;

    // Deterministic in-block reduction -> one partial per block
    red[tid] = acc;
    __syncthreads();
    #pragma unroll
    for (int s = 64; s > 0; s >>= 1) {
        if (tid < s) red[tid] += red[tid + s];
        __syncthreads();
    }
    if (tid == 0) g_partial[b * 64 + blockIdx.x] = red[0];
}

// ---------------------------------------------------------------------------
// Kernel 3: final reduction of 1024 partials; loss = mean(erosion) - 1.
// ---------------------------------------------------------------------------
__global__ void k3_final(float* __restrict__ out) {
    __shared__ float red[512];
    int tid = threadIdx.x;
    red[tid] = g_partial[tid] + g_partial[tid + 512];
    __syncthreads();
    #pragma unroll
    for (int s = 256; s > 0; s >>= 1) {
        if (tid < s) red[tid] += red[tid + s];
        __syncthreads();
    }
    if (tid == 0) out[0] = red[0] * (1.0f / 4194304.0f) - 1.0f;
}

extern "C" void kernel_launch(void* const* d_in, const int* in_sizes, int n_in,
                              void* d_out, int out_size) {
    const float* x = (const float*)d_in[0];
    float* out = (float*)d_out;

    k1_vert<<<dim3(WW / 16, BB), dim3(8, 32)>>>(x);
    k2_horiz<<<dim3(HH / 8, BB), dim3(16, 8)>>>();
    k3_final<<<1, 512>>>(out);
}

// round 16
// speedup vs baseline: 1.1048x; 1.1048x over previous
#include <cuda_runtime.h>
#include <cuda_fp16.h>
#include <math_constants.h>

#define HH 512
#define WW 512
#define BB 16
// window p=35, pad=17
// loss = mean(erosion_35x35(min_c x)) - 1   (erosion = separable min filter)

// Intermediate: vertically eroded field, [B][H][W/2], half2 packs (w, w+1)
__device__ __align__(16) __half2 g_t2[BB * HH * WW / 2];
// Per-block partial sums from kernel 2 (1024 blocks)
__device__ float g_partial[1024];

// ---------------------------------------------------------------------------
// Kernel 1 (R12 geometry — best measured): channel-min of x (fp32 -> fp16)
// fused with vertical min-filter, van Herk chunk 35, half2 packed along W.
// Tile = 64 W cols x 174 rows, PADDED to 176 rows so the loader trip count
// is uniform (2816 = 11 * 256): compile-time bounds -> full unroll -> ptxas
// front-batches the channel LDGs (MLP 3 -> 8+).
// Block = 256 thr (8 warps, all load); chains on warps ty<4.
// grid = (W/64, B, 4) = 512 blocks.
// ---------------------------------------------------------------------------
__global__ __launch_bounds__(256) void k1_vert(const float* __restrict__ x) {
    __shared__ __half2 sm[176 * 32];          // rows 174,175 = padding (INF)

    const int tx  = threadIdx.x;
    const int ty  = threadIdx.y;              // 0..7
    const int tid = ty * 32 + tx;
    const int wc0 = blockIdx.x * 64;
    const int b   = blockIdx.y;
    const int z   = blockIdx.z;
    const int r0  = z * 140;                 // 4 chunks * 35 rows per z-group
    const float INF = CUDART_INF_F;

    // Uniform 11-iteration tile load: rows [r0-17, r0+159) incl. 2 pad rows.
    const float* xb = x + (size_t)b * 3 * HH * WW;
    #pragma unroll
    for (int i = 0; i < 11; i++) {
        int j  = tid + i * 256;               // 0..2815, compile-time bound
        int r  = j >> 4;
        int c4 = j & 15;                      // float4 slot within 64 cols
        int gh = r0 - 17 + r;
        float4 m;
        if ((unsigned)gh < HH) {
            const float4* p = (const float4*)(xb + (size_t)gh * WW + wc0 + c4 * 4);
            float4 a0 = p[0];
            float4 a1 = p[(HH * WW) / 4];
            float4 a2 = p[(2 * HH * WW) / 4];
            m.x = fminf(a0.x, fminf(a1.x, a2.x));
            m.y = fminf(a0.y, fminf(a1.y, a2.y));
            m.z = fminf(a0.z, fminf(a1.z, a2.z));
            m.w = fminf(a0.w, fminf(a1.w, a2.w));
        } else {
            m = make_float4(INF, INF, INF, INF);
        }
        __half2 h0 = __floats2half2_rn(m.x, m.y);
        __half2 h1 = __floats2half2_rn(m.z, m.w);
        uint2 pk = make_uint2(*(unsigned*)&h0, *(unsigned*)&h1);
        *(uint2*)&sm[r * 32 + c4 * 2] = pk;   // STS.64, conflict-free
    }
    __syncthreads();

    // Chains: warps ty<4 only (chunk = z*4+ty); loader warps retire here.
    if (ty >= 4) return;
    const int c    = z * 4 + ty;
    const int base = 35 * c;
    if (base >= HH) return;
    const int lb = 35 * ty + 17;
    const __half2 HINF = __float2half2_rn(CUDART_INF_F);

    // Pass 1: suffix minima (segment reset at k==35)
    __half2 S[35];
    __half2 run = HINF;
    #pragma unroll
    for (int k = 0; k < 52; k++) {
        if (k == 35) run = HINF;
        run = __hmin2(run, sm[(lb + 34 - k) * 32 + tx]);
        if (k >= 17) S[51 - k] = run;
    }

    // Pass 2: prefix minima, combine + store on the fly
    run = HINF;
    const size_t ob = (size_t)b * HH;
    const int wcol = (wc0 >> 1) + tx;
    #pragma unroll
    for (int k = 0; k < 52; k++) {
        if (k == 35) run = HINF;
        run = __hmin2(run, sm[(lb + k) * 32 + tx]);
        if (k >= 17) {
            int i = base + k - 17;
            if (i < HH)
                g_t2[(ob + i) * (WW / 2) + wcol] = __hmin2(S[k - 17], run);
        }
    }
}

// ---------------------------------------------------------------------------
// Kernel 2: horizontal min-filter in PAIR DOMAIN, chunk length 36 (verified
// round-9 math), register-resident chains: 18 independent predicated LDG.64
// per thread, then pure register suffix/prefix/combine.
// Thread (tx = chunk slot 0..15, ty = row 0..7); grid = (H/8, B).
// ---------------------------------------------------------------------------
__global__ __launch_bounds__(128) void k2_horiz() {
    __shared__ float red[128];

    const int tx  = threadIdx.x;              // chunk slot 0..15 (t = tx-1)
    const int ty  = threadIdx.y;              // row-in-tile 0..7
    const int tid = ty * 16 + tx;
    const int h0  = blockIdx.x * 8;
    const int b   = blockIdx.y;
    const __half2 HINF2 = __float2half2_rn(CUDART_INF_F);
    const unsigned INFU = 0x7C007C00u;

    const int t = tx - 1;                     // -1..14
    const __half2* rowp = g_t2 + (size_t)(b * HH + h0 + ty) * (WW / 2);

    // Load chunk t (pairs [18t, 18t+18)) and chunk t+1 into registers.
    __half2 ct[18], dt[18];
    #pragma unroll
    for (int j = 0; j < 9; j++) {
        int p0 = 18 * t + 2 * j;
        uint2 v = make_uint2(INFU, INFU);
        if ((unsigned)p0 < 256u) v = *(const uint2*)(rowp + p0);
        ct[2 * j]     = *(__half2*)&v.x;
        ct[2 * j + 1] = *(__half2*)&v.y;
    }
    #pragma unroll
    for (int j = 0; j < 9; j++) {
        int p0 = 18 * (t + 1) + 2 * j;
        uint2 v = make_uint2(INFU, INFU);
        if ((unsigned)p0 < 256u) v = *(const uint2*)(rowp + p0);
        dt[2 * j]     = *(__half2*)&v.x;
        dt[2 * j + 1] = *(__half2*)&v.y;
    }

    // Backward: suffix pair-minima over chunk t
    __half2 SR[18];
    {
        __half2 run = HINF2;
        #pragma unroll
        for (int u = 17; u >= 0; u--) {
            run = __hmin2(run, ct[u]);
            SR[u] = run;
        }
    }

    // Forward over chunk t+1 + parity combine + accumulate
    __half2 hacc = __float2half2_rn(0.0f);
    __half2 Rp  = HINF2;                      // R[n-1]
    __half2 HPp = HINF2;                      // hmin(R[n-1]) broadcast
    const int obase = 36 * t + 18;
    #pragma unroll
    for (int n = 0; n < 18; n++) {
        __half2 v  = dt[n];
        __half2 Rc = __hmin2(Rp, v);          // R[n]
        __half2 srn = (n < 17) ? SR[n + 1] : HINF2;
        unsigned srnu = *(unsigned*)&srn;
        unsigned swp  = __byte_perm(srnu, srnu, 0x1032);
        __half2 hs = __hmin2(srn, *(__half2*)&swp);   // H_S[n+1] broadcast
        unsigned sru = *(unsigned*)&SR[n];
        unsigned Rcu = *(unsigned*)&Rc;
        unsigned Rpu = *(unsigned*)&Rp;
        unsigned HPu = *(unsigned*)&HPp;
        unsigned Au = __byte_perm(sru, Rcu, 0x5432);  // (SR[n].hi, Rc.lo)
        unsigned Bu = __byte_perm(HPu, Rpu, 0x7610);  // (HPp,      Rp.hi)
        __half2 o = __hmin2(__hmin2(*(__half2*)&Au, *(__half2*)&Bu), hs);
        if ((unsigned)(obase + 2 * n) < 512u)
            hacc = __hadd2(hacc, o);
        unsigned rs = __byte_perm(Rcu, Rcu, 0x1032);
        HPp = __hmin2(Rc, *(__half2*)&rs);    // hmin(R[n]) broadcast
        Rp = Rc;
    }
    float2 e2 = __half22float2(hacc);
    float acc = e2.x + e2.y;

    // Deterministic in-block reduction -> one partial per block
    red[tid] = acc;
    __syncthreads();
    #pragma unroll
    for (int s = 64; s > 0; s >>= 1) {
        if (tid < s) red[tid] += red[tid + s];
        __syncthreads();
    }
    if (tid == 0) g_partial[b * 64 + blockIdx.x] = red[0];
}

// ---------------------------------------------------------------------------
// Kernel 3: final reduction of 1024 partials; loss = mean(erosion) - 1.
// ---------------------------------------------------------------------------
__global__ void k3_final(float* __restrict__ out) {
    __shared__ float red[512];
    int tid = threadIdx.x;
    red[tid] = g_partial[tid] + g_partial[tid + 512];
    __syncthreads();
    #pragma unroll
    for (int s = 256; s > 0; s >>= 1) {
        if (tid < s) red[tid] += red[tid + s];
        __syncthreads();
    }
    if (tid == 0) out[0] = red[0] * (1.0f / 4194304.0f) - 1.0f;
}

extern "C" void kernel_launch(void* const* d_in, const int* in_sizes, int n_in,
                              void* d_out, int out_size) {
    const float* x = (const float*)d_in[0];
    float* out = (float*)d_out;

    k1_vert<<<dim3(WW / 64, BB, 4), dim3(32, 8)>>>(x);
    k2_horiz<<<dim3(HH / 8, BB), dim3(16, 8)>>>();
    k3_final<<<1, 512>>>(out);
}